// round 2
// baseline (speedup 1.0000x reference)
#include <cuda_runtime.h>
#include <math.h>

#define BB 8
#define CC 2048
#define PP 64
#define DD 512
#define KK 512
#define TT 12
#define VV 20000
#define T1 13

// ---------------- scratch (device globals, no allocs) ----------------
__device__ float g_Vmean[BB*CC];
__device__ float g_h[BB*DD];
__device__ float g_c[BB*DD];
__device__ float g_hW[2*BB*KK];              // [0]=h@W_hc, [1]=h@W_hs
__device__ float g_betalogit[BB*CC];
__device__ float g_beta[BB*CC];
__device__ float g_Mpart[4*BB*PP*KK];        // 4 c-split partials of einsum
__device__ float g_alphalogit[BB*PP];
__device__ float g_alpha[BB*PP];
__device__ float g_awe[BB*CC];
__device__ float g_gates[BB*4*DD];

// ---------------- helpers ----------------
__device__ __forceinline__ float warp_sum(float v){
  v += __shfl_down_sync(0xffffffffu, v, 16);
  v += __shfl_down_sync(0xffffffffu, v, 8);
  v += __shfl_down_sync(0xffffffffu, v, 4);
  v += __shfl_down_sync(0xffffffffu, v, 2);
  v += __shfl_down_sync(0xffffffffu, v, 1);
  return v;
}
__device__ __forceinline__ float tanh_fast(float x){
  float y; asm("tanh.approx.f32 %0, %1;" : "=f"(y) : "f"(x)); return y;
}

// ---------------- setup kernels ----------------
// mean over P=64 per (b,c) row; warp per row
__global__ void k_vmean(const float* __restrict__ enc){
  int w = blockIdx.x*8 + (threadIdx.x>>5);   // 0..16383
  int lane = threadIdx.x & 31;
  const float* r = enc + (size_t)w*PP;
  float s = r[lane] + r[lane+32];
  s = warp_sum(s);
  if(lane==0) g_Vmean[w] = s * (1.0f/64.0f);
}

// h0/c0 = Vmean @ W_init.T + b ; warp per output
__global__ void k_init(const float* __restrict__ Wh, const float* __restrict__ bh,
                       const float* __restrict__ Wc, const float* __restrict__ bc){
  int gw = blockIdx.x*4 + (threadIdx.x>>5);  // 0..8191
  int lane = threadIdx.x & 31;
  int m = gw >> 12;
  int rem = gw & 4095;
  int b = rem >> 9;
  int d = rem & 511;
  const float* W = m ? Wc : Wh;
  const float* vm = g_Vmean + b*CC;
  const float* wr = W + (size_t)d*CC;
  float acc = 0.f;
  #pragma unroll 8
  for(int c=lane;c<CC;c+=32) acc = fmaf(vm[c], wr[c], acc);
  acc = warp_sum(acc);
  if(lane==0){
    if(m) g_c[b*DD+d] = acc + bc[d];
    else  g_h[b*DD+d] = acc + bh[d];
  }
}

// tail of output: encoded_captions, decode_lengths, alphas(zeros), sort_ind
__global__ void k_tail(float* __restrict__ out, long long out_size,
                       const int* __restrict__ caps, const int* __restrict__ caplen){
  long long base = (long long)BB*TT*VV;      // 1,920,000
  int idx = blockIdx.x*blockDim.x + threadIdx.x;
  int total = BB*T1 + BB + BB*TT*PP + BB;    // 6264
  if(idx >= total) return;
  long long pos = base + idx;
  if(pos >= out_size) return;
  float val;
  if(idx < BB*T1)                      val = (float)caps[idx];
  else if(idx < BB*T1 + BB)            val = (float)(caplen[idx - BB*T1] - 1);
  else if(idx < BB*T1 + BB + BB*TT*PP) val = 0.f;
  else                                 val = (float)(idx - (BB*T1 + BB + BB*TT*PP));
  out[pos] = val;
}

// ---------------- per-step kernels ----------------
// g_hW[m][b][k] = sum_d h[b,d] * W[d,k]   (m=0: W_hc, m=1: W_hs)
__global__ void k_hW(const float* __restrict__ Whc, const float* __restrict__ Whs){
  __shared__ float sh[DD];
  int bx = blockIdx.x;            // 64 blocks: b(3b) m(1b) kc(2b)
  int b  = bx >> 3;
  int m  = (bx >> 2) & 1;
  int kc = bx & 3;
  int tid = threadIdx.x;          // 128 threads
  for(int i=tid;i<DD;i+=128) sh[i] = g_h[b*DD+i];
  __syncthreads();
  const float* W = m ? Whs : Whc;
  int k = kc*128 + tid;
  float acc = 0.f;
  #pragma unroll 8
  for(int d=0; d<DD; d++)
    acc = fmaf(sh[d], W[(size_t)d*KK + k], acc);
  g_hW[(m*BB + b)*KK + k] = acc;
}

// beta logits: l[b,c] = sum_k tanh(Vmean[b,c]*W_c[k] + b_c[k] + hWhc[b,k]) * W_ihat[k] + b_ihat
__global__ void k_betalogit(const float* __restrict__ W_c, const float* __restrict__ b_c,
                            const float* __restrict__ W_ihat, const float* __restrict__ b_ihat){
  __shared__ float swc[KK], sbase[KK], swi[KK];
  int b = blockIdx.y;
  int tid = threadIdx.x;
  for(int i=tid;i<KK;i+=256){
    swc[i]   = W_c[i];
    sbase[i] = b_c[i] + g_hW[b*KK + i];
    swi[i]   = W_ihat[i];
  }
  __syncthreads();
  int c = blockIdx.x*8 + (tid>>5);
  int lane = tid & 31;
  float vm = g_Vmean[b*CC + c];
  float acc = 0.f;
  #pragma unroll
  for(int kk=0;kk<16;kk++){
    int k = kk*32 + lane;
    acc = fmaf(tanh_fast(fmaf(vm, swc[k], sbase[k])), swi[k], acc);
  }
  acc = warp_sum(acc);
  if(lane==0) g_betalogit[b*CC + c] = acc + b_ihat[0];
}

// softmax over batch axis per channel
__global__ void k_betasoftmax(){
  int c = blockIdx.x*256 + threadIdx.x;
  float l[BB]; float mx = -1e30f;
  #pragma unroll
  for(int b=0;b<BB;b++){ l[b] = g_betalogit[b*CC+c]; mx = fmaxf(mx, l[b]); }
  float s = 0.f;
  #pragma unroll
  for(int b=0;b<BB;b++){ l[b] = expf(l[b]-mx); s += l[b]; }
  float inv = 1.f/s;
  #pragma unroll
  for(int b=0;b<BB;b++) g_beta[b*CC+c] = l[b]*inv;
}

// einsum partial: Mpart[cs][b][p][k] = sum_{c in cs-slice} enc[b,c,p]*beta[b,c]*W_s[c,k]
// grid (kt=4, b=8, cs=4), block 256 (16x16 threads), micro-tile 4p x 8k
__global__ void k_einsum(const float* __restrict__ enc, const float* __restrict__ W_s){
  __shared__ float shA[16*64];
  __shared__ float shB[16*128];
  int kt = blockIdx.x, b = blockIdx.y, cs = blockIdx.z;
  int tid = threadIdx.x;
  int tx = tid & 15, ty = tid >> 4;
  int kbase = kt*128;
  int c0 = cs*512;
  float acc[4][8];
  #pragma unroll
  for(int i=0;i<4;i++)
    #pragma unroll
    for(int j=0;j<8;j++) acc[i][j]=0.f;

  const float* encB  = enc + (size_t)b*CC*PP;
  const float* betaB = g_beta + b*CC;

  for(int cb=0; cb<512; cb+=16){
    { // stage cw chunk (16c x 64p) and W_s chunk (16c x 128k)
      int i0 = tid;  int ccA = i0 >> 4, pA = i0 & 15;
      int cA = c0 + cb + ccA;
      float4 av = *(const float4*)(encB + (size_t)cA*PP + pA*4);
      float bv = betaB[cA];
      ((float4*)shA)[i0] = make_float4(av.x*bv, av.y*bv, av.z*bv, av.w*bv);
      int j0 = tid;       int cB0 = j0>>5, kq0 = j0&31;
      int j1 = tid+256;   int cB1 = j1>>5, kq1 = j1&31;
      ((float4*)shB)[j0] = *(const float4*)(W_s + (size_t)(c0+cb+cB0)*KK + kbase + kq0*4);
      ((float4*)shB)[j1] = *(const float4*)(W_s + (size_t)(c0+cb+cB1)*KK + kbase + kq1*4);
    }
    __syncthreads();
    #pragma unroll
    for(int cc=0; cc<16; cc++){
      float4 av  = ((const float4*)shA)[cc*16 + ty];
      float4 bv0 = ((const float4*)shB)[cc*32 + tx*2];
      float4 bv1 = ((const float4*)shB)[cc*32 + tx*2 + 1];
      float a[4]  = {av.x, av.y, av.z, av.w};
      float bw[8] = {bv0.x,bv0.y,bv0.z,bv0.w, bv1.x,bv1.y,bv1.z,bv1.w};
      #pragma unroll
      for(int i=0;i<4;i++)
        #pragma unroll
        for(int j=0;j<8;j++) acc[i][j] = fmaf(a[i], bw[j], acc[i][j]);
    }
    __syncthreads();
  }
  float* Mout = g_Mpart + ((size_t)cs*BB + b)*PP*KK + kbase + tx*8;
  #pragma unroll
  for(int i=0;i<4;i++){
    int p = ty*4 + i;
    float4 v0 = make_float4(acc[i][0],acc[i][1],acc[i][2],acc[i][3]);
    float4 v1 = make_float4(acc[i][4],acc[i][5],acc[i][6],acc[i][7]);
    *(float4*)(Mout + (size_t)p*KK)     = v0;
    *(float4*)(Mout + (size_t)p*KK + 4) = v1;
  }
}

// alpha logits: sum 4 partials, add biases + hWhs, tanh, reduce by W_i
__global__ void k_alphalogit(const float* __restrict__ b_s, const float* __restrict__ W_i,
                             const float* __restrict__ b_i){
  int gw = blockIdx.x*8 + (threadIdx.x>>5);    // 0..511
  int lane = threadIdx.x & 31;
  int b = gw >> 6, p = gw & 63;
  const float* m0 = g_Mpart + ((size_t)b*PP + p)*KK;
  const float* hws = g_hW + BB*KK + b*KK;
  const size_t PS = (size_t)BB*PP*KK;
  float acc = 0.f;
  #pragma unroll
  for(int kk=0;kk<16;kk++){
    int k = kk*32 + lane;
    float m = m0[k] + m0[PS + k] + m0[2*PS + k] + m0[3*PS + k] + b_s[k] + hws[k];
    acc = fmaf(tanh_fast(m), W_i[k], acc);
  }
  acc = warp_sum(acc);
  if(lane==0) g_alphalogit[b*PP + p] = acc + b_i[0];
}

__global__ void k_alphasoftmax(){
  int p = threadIdx.x;   // 64 threads
  float l[BB]; float mx = -1e30f;
  #pragma unroll
  for(int b=0;b<BB;b++){ l[b] = g_alphalogit[b*PP+p]; mx = fmaxf(mx, l[b]); }
  float s = 0.f;
  #pragma unroll
  for(int b=0;b<BB;b++){ l[b] = expf(l[b]-mx); s += l[b]; }
  float inv = 1.f/s;
  #pragma unroll
  for(int b=0;b<BB;b++) g_alpha[b*PP+p] = l[b]*inv;
}

// awe[b,c] = beta[b,c]/64 * sum_p enc[b,c,p]*alpha[b,p]
__global__ void k_awe(const float* __restrict__ enc){
  __shared__ float sal[PP];
  int b = blockIdx.y;
  int tid = threadIdx.x;
  if(tid < PP) sal[tid] = g_alpha[b*PP + tid];
  __syncthreads();
  int c = blockIdx.x*8 + (tid>>5);
  int lane = tid & 31;
  const float* r = enc + ((size_t)b*CC + c)*PP;
  float s = fmaf(r[lane], sal[lane], r[lane+32]*sal[lane+32]);
  s = warp_sum(s);
  if(lane==0) g_awe[b*CC+c] = g_beta[b*CC+c] * s * (1.0f/64.0f);
}

// gates[b,j] = x@W_ih.T + h@W_hh.T + biases; x = [emb_tok | awe], len 2560; h len 512
// warp handles 4 j's x all 8 b; x for all b in dynamic shared (96KB)
__global__ void k_gates(const float* __restrict__ Wih, const float* __restrict__ Whh,
                        const float* __restrict__ bih, const float* __restrict__ bhh,
                        const float* __restrict__ emb, const int* __restrict__ caps, int t){
  extern __shared__ float shx[];   // 8 * 3072
  int tid = threadIdx.x;
  #pragma unroll
  for(int b=0;b<BB;b++){
    int tok = caps[b*T1 + t];
    const float* er = emb + (size_t)tok*DD;
    float* xb = shx + b*3072;
    for(int i=tid;i<512;i+=256)  xb[i]        = er[i];
    for(int i=tid;i<2048;i+=256) xb[512+i]    = g_awe[b*CC+i];
    for(int i=tid;i<512;i+=256)  xb[2560+i]   = g_h[b*DD+i];
  }
  __syncthreads();
  int w = blockIdx.x*8 + (tid>>5);   // 0..511
  int lane = tid & 31;
  int j0 = w*4;
  float acc[4][8];
  #pragma unroll
  for(int vi=0;vi<4;vi++)
    #pragma unroll
    for(int b=0;b<8;b++) acc[vi][b]=0.f;
  for(int kk=0;kk<96;kk++){
    int k = kk*32 + lane;
    float wv[4];
    if(kk < 80){
      #pragma unroll
      for(int vi=0;vi<4;vi++) wv[vi] = Wih[(size_t)(j0+vi)*2560 + k];
    } else {
      #pragma unroll
      for(int vi=0;vi<4;vi++) wv[vi] = Whh[(size_t)(j0+vi)*512 + (k-2560)];
    }
    #pragma unroll
    for(int b=0;b<8;b++){
      float xv = shx[b*3072 + k];
      #pragma unroll
      for(int vi=0;vi<4;vi++) acc[vi][b] = fmaf(wv[vi], xv, acc[vi][b]);
    }
  }
  #pragma unroll
  for(int vi=0;vi<4;vi++){
    #pragma unroll
    for(int b=0;b<8;b++){
      float s = warp_sum(acc[vi][b]);
      if(lane==0) g_gates[b*2048 + j0+vi] = s + bih[j0+vi] + bhh[j0+vi];
    }
  }
}

// LSTM cell update (precise math; feeds predictions directly)
__global__ void k_lstm(){
  int b = blockIdx.x, d = threadIdx.x;
  float gi = g_gates[b*2048 + d];
  float gf = g_gates[b*2048 + 512 + d];
  float gg = g_gates[b*2048 + 1024 + d];
  float go = g_gates[b*2048 + 1536 + d];
  float si = 1.f/(1.f+expf(-gi));
  float sf = 1.f/(1.f+expf(-gf));
  float so = 1.f/(1.f+expf(-go));
  float cn = sf*g_c[b*DD+d] + si*tanhf(gg);
  g_c[b*DD+d] = cn;
  g_h[b*DD+d] = so*tanhf(cn);
}

// preds[b,v] = h@W_fc[v].T + b_fc[v]; warp handles 4 v's x 8 b, lanes over k
__global__ void k_preds(const float* __restrict__ Wfc, const float* __restrict__ bfc,
                        float* __restrict__ out, int t){
  __shared__ float shh[BB*DD];  // 16KB
  int tid = threadIdx.x;
  for(int i=tid;i<BB*DD;i+=256) shh[i] = g_h[i];
  __syncthreads();
  int w = blockIdx.x*8 + (tid>>5);   // 0..4999
  int lane = tid & 31;
  int v0 = w*4;
  float acc[4][8];
  #pragma unroll
  for(int vi=0;vi<4;vi++)
    #pragma unroll
    for(int b=0;b<8;b++) acc[vi][b]=0.f;
  const float* wr = Wfc + (size_t)v0*DD;
  #pragma unroll 2
  for(int kk=0;kk<16;kk++){
    int k = kk*32 + lane;
    float wv[4];
    #pragma unroll
    for(int vi=0;vi<4;vi++) wv[vi] = wr[(size_t)vi*DD + k];
    #pragma unroll
    for(int b=0;b<8;b++){
      float hv = shh[b*DD + k];
      #pragma unroll
      for(int vi=0;vi<4;vi++) acc[vi][b] = fmaf(wv[vi], hv, acc[vi][b]);
    }
  }
  #pragma unroll
  for(int vi=0;vi<4;vi++){
    #pragma unroll
    for(int b=0;b<8;b++){
      float s = warp_sum(acc[vi][b]);
      if(lane==0)
        out[(size_t)b*(TT*VV) + (size_t)t*VV + v0 + vi] = s + bfc[v0+vi];
    }
  }
}

// ---------------- launch ----------------
extern "C" void kernel_launch(void* const* d_in, const int* in_sizes, int n_in,
                              void* d_out, int out_size){
  const float* enc      = (const float*)d_in[0];
  const int*   caps     = (const int*)  d_in[1];
  const int*   caplen   = (const int*)  d_in[2];
  const float* W_c      = (const float*)d_in[3];
  const float* W_hc     = (const float*)d_in[4];
  const float* W_ihat   = (const float*)d_in[5];
  const float* b_c      = (const float*)d_in[6];
  const float* b_ihat   = (const float*)d_in[7];
  const float* W_s      = (const float*)d_in[8];
  const float* W_hs     = (const float*)d_in[9];
  const float* W_i      = (const float*)d_in[10];
  const float* b_s      = (const float*)d_in[11];
  const float* b_i      = (const float*)d_in[12];
  const float* emb      = (const float*)d_in[13];
  const float* W_ih     = (const float*)d_in[14];
  const float* W_hh     = (const float*)d_in[15];
  const float* b_ih     = (const float*)d_in[16];
  const float* b_hh     = (const float*)d_in[17];
  const float* W_init_h = (const float*)d_in[18];
  const float* b_init_h = (const float*)d_in[19];
  const float* W_init_c = (const float*)d_in[20];
  const float* b_init_c = (const float*)d_in[21];
  const float* W_fc     = (const float*)d_in[22];
  const float* b_fc     = (const float*)d_in[23];
  float* out = (float*)d_out;

  static bool attr_set = false;
  if(!attr_set){
    cudaFuncSetAttribute(k_gates, cudaFuncAttributeMaxDynamicSharedMemorySize, BB*3072*4);
    attr_set = true;
  }

  k_vmean<<<2048,256>>>(enc);
  k_init<<<2048,128>>>(W_init_h, b_init_h, W_init_c, b_init_c);
  k_tail<<<25,256>>>(out, (long long)out_size, caps, caplen);

  for(int t=0;t<TT;t++){
    k_hW<<<64,128>>>(W_hc, W_hs);
    k_betalogit<<<dim3(256,8),256>>>(W_c, b_c, W_ihat, b_ihat);
    k_betasoftmax<<<8,256>>>();
    k_einsum<<<dim3(4,8,4),256>>>(enc, W_s);
    k_alphalogit<<<64,256>>>(b_s, W_i, b_i);
    k_alphasoftmax<<<1,64>>>();
    k_awe<<<dim3(256,8),256>>>(enc);
    k_gates<<<64,256,BB*3072*4>>>(W_ih, W_hh, b_ih, b_hh, emb, caps, t);
    k_lstm<<<8,512>>>();
    k_preds<<<625,256>>>(W_fc, b_fc, out, t);
  }
}

// round 3
// speedup vs baseline: 1.1312x; 1.1312x over previous
#include <cuda_runtime.h>
#include <math.h>

#define BB 8
#define CC 2048
#define PP 64
#define DD 512
#define KK 512
#define TT 12
#define VV 20000
#define T1 13

// ---------------- scratch (device globals, no allocs) ----------------
__device__ float g_Vmean[BB*CC];
__device__ float g_h[2][BB*DD];
__device__ float g_c[2][BB*DD];
__device__ float g_hWpart[4][2][BB][KK];     // [dsplit][m][b][k], m=0:W_hc, 1:W_hs
__device__ float g_beta[BB*CC];
__device__ float g_Mpart[8][BB][PP][KK];     // 8 c-split partials of einsum
__device__ float g_alphalogit[BB*PP];
__device__ float g_awe[BB*CC];

// ---------------- helpers ----------------
__device__ __forceinline__ float warp_sum(float v){
  v += __shfl_down_sync(0xffffffffu, v, 16);
  v += __shfl_down_sync(0xffffffffu, v, 8);
  v += __shfl_down_sync(0xffffffffu, v, 4);
  v += __shfl_down_sync(0xffffffffu, v, 2);
  v += __shfl_down_sync(0xffffffffu, v, 1);
  return v;
}
__device__ __forceinline__ float tanh_fast(float x){
  float y; asm("tanh.approx.f32 %0, %1;" : "=f"(y) : "f"(x)); return y;
}
// Butterfly pack-reduce: N per-lane accumulators (N power of 2, <=32).
// Returns: lane L holds total sum of accumulator (L & (N-1)).
template<int N>
__device__ __forceinline__ float reduceN(float* a){
  unsigned L = threadIdx.x & 31;
  #pragma unroll
  for(int off=16; off>=1; off>>=1){
    if(2*off > N){
      #pragma unroll
      for(int i=0;i<N;i++) a[i] += __shfl_xor_sync(0xffffffffu, a[i], off);
    } else {
      #pragma unroll
      for(int i=0;i<off;i++){
        float send = (L & off) ? a[i] : a[i+off];
        float recv = __shfl_xor_sync(0xffffffffu, send, off);
        a[i] = ((L & off) ? a[i+off] : a[i]) + recv;
      }
    }
  }
  return a[0];
}

// ---------------- setup kernels ----------------
__global__ void k_vmean(const float* __restrict__ enc){
  int w = blockIdx.x*8 + (threadIdx.x>>5);
  int lane = threadIdx.x & 31;
  const float* r = enc + (size_t)w*PP;
  float s = r[lane] + r[lane+32];
  s = warp_sum(s);
  if(lane==0) g_Vmean[w] = s * (1.0f/64.0f);
}

__global__ void k_init(const float* __restrict__ Wh, const float* __restrict__ bh,
                       const float* __restrict__ Wc, const float* __restrict__ bc){
  int gw = blockIdx.x*4 + (threadIdx.x>>5);
  int lane = threadIdx.x & 31;
  int m = gw >> 12;
  int rem = gw & 4095;
  int b = rem >> 9;
  int d = rem & 511;
  const float* W = m ? Wc : Wh;
  const float* vm = g_Vmean + b*CC;
  const float* wr = W + (size_t)d*CC;
  float acc = 0.f;
  #pragma unroll 8
  for(int c=lane;c<CC;c+=32) acc = fmaf(vm[c], wr[c], acc);
  acc = warp_sum(acc);
  if(lane==0){
    if(m) g_c[0][b*DD+d] = acc + bc[d];
    else  g_h[0][b*DD+d] = acc + bh[d];
  }
}

__global__ void k_tail(float* __restrict__ out, long long out_size,
                       const int* __restrict__ caps, const int* __restrict__ caplen){
  long long base = (long long)BB*TT*VV;
  int idx = blockIdx.x*blockDim.x + threadIdx.x;
  int total = BB*T1 + BB + BB*TT*PP + BB;
  if(idx >= total) return;
  long long pos = base + idx;
  if(pos >= out_size) return;
  float val;
  if(idx < BB*T1)                      val = (float)caps[idx];
  else if(idx < BB*T1 + BB)            val = (float)(caplen[idx - BB*T1] - 1);
  else if(idx < BB*T1 + BB + BB*TT*PP) val = 0.f;
  else                                 val = (float)(idx - (BB*T1 + BB + BB*TT*PP));
  out[pos] = val;
}

// ---------------- per-step kernels ----------------
// hWpart[dt][m][b][k] = sum_{d in dt-slice} h[b,d]*W[d,k]; W read ONCE (shared across b)
__global__ void k_hW(const float* __restrict__ Whc, const float* __restrict__ Whs, int hb){
  // grid 128 = m(2) x kt(16) x dt(4); block 256 = 32 k-lanes x 8 d-subgroups
  int bx = blockIdx.x;
  int m  = bx >> 6;
  int kt = (bx >> 2) & 15;
  int dt = bx & 3;
  int tid = threadIdx.x;
  int kl = tid & 31;
  int ds = tid >> 5;
  int k = kt*32 + kl;
  const float* W = m ? Whs : Whc;
  __shared__ float shh[8][128];
  __shared__ float red[8][8][32];
  for(int i=tid;i<8*128;i+=256){
    int b=i>>7, dd=i&127;
    shh[b][dd] = g_h[hb][b*DD + dt*128 + dd];
  }
  __syncthreads();
  float acc[8];
  #pragma unroll
  for(int b=0;b<8;b++) acc[b]=0.f;
  #pragma unroll 4
  for(int di=0; di<16; di++){
    int dd = ds*16 + di;
    float wv = W[(size_t)(dt*128+dd)*KK + k];
    #pragma unroll
    for(int b=0;b<8;b++) acc[b] = fmaf(shh[b][dd], wv, acc[b]);
  }
  #pragma unroll
  for(int b=0;b<8;b++) red[ds][b][kl] = acc[b];
  __syncthreads();
  // tid -> (b=ds, kl): sum over 8 subgroups
  float s = 0.f;
  #pragma unroll
  for(int q=0;q<8;q++) s += red[q][ds][kl];
  g_hWpart[dt][m][ds][k] = s;
}

// beta logits + softmax over batch, fused. warp per channel, 8 channels/block.
__global__ void k_betafused(const float* __restrict__ W_c, const float* __restrict__ b_c,
                            const float* __restrict__ W_ihat, const float* __restrict__ b_ihat){
  __shared__ float swc[KK], swi[KK], sbase[8][KK];
  int tid = threadIdx.x;
  for(int i=tid;i<KK;i+=256){ swc[i]=W_c[i]; swi[i]=W_ihat[i]; }
  for(int i=tid;i<8*KK;i+=256){
    int b=i>>9, k=i&511;
    sbase[b][k] = b_c[k] + g_hWpart[0][0][b][k] + g_hWpart[1][0][b][k]
                         + g_hWpart[2][0][b][k] + g_hWpart[3][0][b][k];
  }
  __syncthreads();
  int wid = tid>>5, lane = tid&31;
  int c = blockIdx.x*8 + wid;
  float a[8];
  #pragma unroll
  for(int b=0;b<8;b++){
    float vm = g_Vmean[b*CC + c];
    float acc = 0.f;
    #pragma unroll
    for(int kk=0;kk<16;kk++){
      int k = kk*32 + lane;
      acc = fmaf(tanh_fast(fmaf(vm, swc[k], sbase[b][k])), swi[k], acc);
    }
    a[b] = acc;
  }
  float l = reduceN<8>(a) + b_ihat[0];   // lane&7 = batch (replicated over 4 groups)
  // softmax over b within 8-lane segments
  float mx = l;
  #pragma unroll
  for(int off=1;off<8;off<<=1) mx = fmaxf(mx, __shfl_xor_sync(0xffffffffu, mx, off, 8));
  float e = expf(l - mx);
  float s = e;
  #pragma unroll
  for(int off=1;off<8;off<<=1) s += __shfl_xor_sync(0xffffffffu, s, off, 8);
  if(lane < 8) g_beta[lane*CC + c] = e / s;
}

// einsum partial: Mpart[cs][b][p][k] = sum_{c in 256-slice} enc[b,c,p]*beta[b,c]*W_s[c,k]
// grid (kt=4, b=8, cs=8), block 256 (16x16), micro-tile 4p x 8k
__global__ void k_einsum(const float* __restrict__ enc, const float* __restrict__ W_s){
  __shared__ float shA[16*64];
  __shared__ float shB[16*128];
  int kt = blockIdx.x, b = blockIdx.y, cs = blockIdx.z;
  int tid = threadIdx.x;
  int tx = tid & 15, ty = tid >> 4;
  int kbase = kt*128;
  int c0 = cs*256;
  float acc[4][8];
  #pragma unroll
  for(int i=0;i<4;i++)
    #pragma unroll
    for(int j=0;j<8;j++) acc[i][j]=0.f;

  const float* encB  = enc + (size_t)b*CC*PP;
  const float* betaB = g_beta + b*CC;

  for(int cb=0; cb<256; cb+=16){
    {
      int ccA = tid >> 4, pA = tid & 15;
      int cA = c0 + cb + ccA;
      float4 av = *(const float4*)(encB + (size_t)cA*PP + pA*4);
      float bv = betaB[cA];
      ((float4*)shA)[tid] = make_float4(av.x*bv, av.y*bv, av.z*bv, av.w*bv);
      int cB0 = tid>>5, kq0 = tid&31;
      int j1 = tid+256; int cB1 = j1>>5, kq1 = j1&31;
      ((float4*)shB)[tid] = *(const float4*)(W_s + (size_t)(c0+cb+cB0)*KK + kbase + kq0*4);
      ((float4*)shB)[j1]  = *(const float4*)(W_s + (size_t)(c0+cb+cB1)*KK + kbase + kq1*4);
    }
    __syncthreads();
    #pragma unroll
    for(int cc=0; cc<16; cc++){
      float4 av  = ((const float4*)shA)[cc*16 + ty];
      float4 bv0 = ((const float4*)shB)[cc*32 + tx*2];
      float4 bv1 = ((const float4*)shB)[cc*32 + tx*2 + 1];
      float a[4]  = {av.x, av.y, av.z, av.w};
      float bw[8] = {bv0.x,bv0.y,bv0.z,bv0.w, bv1.x,bv1.y,bv1.z,bv1.w};
      #pragma unroll
      for(int i=0;i<4;i++)
        #pragma unroll
        for(int j=0;j<8;j++) acc[i][j] = fmaf(a[i], bw[j], acc[i][j]);
    }
    __syncthreads();
  }
  float* Mout = &g_Mpart[cs][b][0][0] + kbase + tx*8;
  #pragma unroll
  for(int i=0;i<4;i++){
    int p = ty*4 + i;
    *(float4*)(Mout + (size_t)p*KK)     = make_float4(acc[i][0],acc[i][1],acc[i][2],acc[i][3]);
    *(float4*)(Mout + (size_t)p*KK + 4) = make_float4(acc[i][4],acc[i][5],acc[i][6],acc[i][7]);
  }
}

// alpha logits: sum 8 partials + base, tanh, reduce by W_i. grid 64 = b(8) x pchunk(8)
__global__ void k_alphalogit(const float* __restrict__ b_s, const float* __restrict__ W_i,
                             const float* __restrict__ b_i){
  __shared__ float sbase[KK], sWi[KK];
  int b  = blockIdx.x >> 3;
  int p0 = (blockIdx.x & 7) * 8;
  int tid = threadIdx.x;
  for(int k=tid;k<KK;k+=256){
    sbase[k] = b_s[k] + g_hWpart[0][1][b][k] + g_hWpart[1][1][b][k]
                      + g_hWpart[2][1][b][k] + g_hWpart[3][1][b][k];
    sWi[k] = W_i[k];
  }
  __syncthreads();
  int wid = tid>>5, lane = tid&31;
  int p = p0 + wid;
  const float* m0 = &g_Mpart[0][b][p][0];
  const size_t PS = (size_t)BB*PP*KK;
  float acc = 0.f;
  #pragma unroll
  for(int kk=0;kk<16;kk++){
    int k = kk*32 + lane;
    float m = sbase[k];
    #pragma unroll
    for(int s=0;s<8;s++) m += m0[s*PS + k];
    acc = fmaf(tanh_fast(m), sWi[k], acc);
  }
  acc = warp_sum(acc);
  if(lane==0) g_alphalogit[b*PP + p] = acc + b_i[0];
}

// awe[b,c] = beta[b,c]/64 * sum_p enc[b,c,p]*alpha[b,p]; alpha softmax fused in.
__global__ void k_awe(const float* __restrict__ enc){
  __shared__ float sal[PP];
  int b = blockIdx.y;
  int tid = threadIdx.x;
  if(tid < PP){
    float l[BB]; float mx = -1e30f;
    #pragma unroll
    for(int bb=0;bb<BB;bb++){ l[bb] = g_alphalogit[bb*PP+tid]; mx = fmaxf(mx, l[bb]); }
    float s = 0.f;
    #pragma unroll
    for(int bb=0;bb<BB;bb++) s += expf(l[bb]-mx);
    sal[tid] = expf(l[b]-mx) / s;
  }
  __syncthreads();
  int c = blockIdx.x*8 + (tid>>5);
  int lane = tid & 31;
  const float* r = enc + ((size_t)b*CC + c)*PP;
  float s = fmaf(r[lane], sal[lane], r[lane+32]*sal[lane+32]);
  s = warp_sum(s);
  if(lane==0) g_awe[b*CC+c] = g_beta[b*CC+c] * s * (1.0f/64.0f);
}

// gates + LSTM cell fused. warp w handles d = w; 4 gate-types x 8 batches = 32 accs.
// reads h/c from buf hb, writes h/c to buf nb (ping-pong; no intra-kernel race).
__global__ void k_gates(const float* __restrict__ Wih, const float* __restrict__ Whh,
                        const float* __restrict__ bih, const float* __restrict__ bhh,
                        const float* __restrict__ emb, const int* __restrict__ caps,
                        int t, int hb, int nb){
  extern __shared__ float shx[];   // 8 * 3072
  int tid = threadIdx.x;
  #pragma unroll
  for(int b=0;b<BB;b++){
    int tok = caps[b*T1 + t];
    const float* er = emb + (size_t)tok*DD;
    float* xb = shx + b*3072;
    for(int i=tid;i<512;i+=256)  xb[i]      = er[i];
    for(int i=tid;i<2048;i+=256) xb[512+i]  = g_awe[b*CC+i];
    for(int i=tid;i<512;i+=256)  xb[2560+i] = g_h[hb][b*DD+i];
  }
  __syncthreads();
  int w = blockIdx.x*8 + (tid>>5);   // d index 0..511
  int lane = tid & 31;
  int d = w;
  float a[32];
  #pragma unroll
  for(int i=0;i<32;i++) a[i]=0.f;
  for(int kk=0;kk<96;kk++){
    int k = kk*32 + lane;
    float wv[4];
    if(kk < 80){
      #pragma unroll
      for(int vi=0;vi<4;vi++) wv[vi] = Wih[(size_t)(d + vi*512)*2560 + k];
    } else {
      #pragma unroll
      for(int vi=0;vi<4;vi++) wv[vi] = Whh[(size_t)(d + vi*512)*512 + (k-2560)];
    }
    #pragma unroll
    for(int b=0;b<8;b++){
      float xv = shx[b*3072 + k];
      #pragma unroll
      for(int vi=0;vi<4;vi++) a[vi*8+b] = fmaf(wv[vi], xv, a[vi*8+b]);
    }
  }
  float r = reduceN<32>(a);          // lane j: gate (j>>3), batch (j&7)
  int vi = lane>>3;
  int row = d + vi*512;
  float gv = r + bih[row] + bhh[row];
  int bl = lane & 7;
  float gi = __shfl_sync(0xffffffffu, gv, bl);
  float gf = __shfl_sync(0xffffffffu, gv, 8 + bl);
  float gg = __shfl_sync(0xffffffffu, gv, 16 + bl);
  float go = __shfl_sync(0xffffffffu, gv, 24 + bl);
  if(lane < 8){
    int b = lane;
    float si = 1.f/(1.f+expf(-gi));
    float sf = 1.f/(1.f+expf(-gf));
    float so = 1.f/(1.f+expf(-go));
    float cn = sf*g_c[hb][b*DD+d] + si*tanhf(gg);
    g_c[nb][b*DD+d] = cn;
    g_h[nb][b*DD+d] = so*tanhf(cn);
  }
}

// preds[b,v] = h@W_fc[v].T + b_fc[v]; warp: 4 v x 8 b, butterfly reduce
__global__ void k_preds(const float* __restrict__ Wfc, const float* __restrict__ bfc,
                        float* __restrict__ out, int t, int hb){
  __shared__ float shh[BB*DD];
  int tid = threadIdx.x;
  for(int i=tid;i<BB*DD;i+=256) shh[i] = g_h[hb][i];
  __syncthreads();
  int w = blockIdx.x*8 + (tid>>5);
  int lane = tid & 31;
  int v0 = w*4;
  float a[32];
  #pragma unroll
  for(int i=0;i<32;i++) a[i]=0.f;
  const float* wr = Wfc + (size_t)v0*DD;
  #pragma unroll 2
  for(int kk=0;kk<16;kk++){
    int k = kk*32 + lane;
    float wv[4];
    #pragma unroll
    for(int vi=0;vi<4;vi++) wv[vi] = wr[(size_t)vi*DD + k];
    #pragma unroll
    for(int b=0;b<8;b++){
      float hv = shh[b*DD + k];
      #pragma unroll
      for(int vi=0;vi<4;vi++) a[vi*8+b] = fmaf(wv[vi], hv, a[vi*8+b]);
    }
  }
  float r = reduceN<32>(a);          // lane j: v=v0+(j>>3), b=j&7
  int vi = lane>>3, b = lane&7;
  out[(size_t)b*(TT*VV) + (size_t)t*VV + v0 + vi] = r + bfc[v0+vi];
}

// ---------------- launch ----------------
extern "C" void kernel_launch(void* const* d_in, const int* in_sizes, int n_in,
                              void* d_out, int out_size){
  const float* enc      = (const float*)d_in[0];
  const int*   caps     = (const int*)  d_in[1];
  const int*   caplen   = (const int*)  d_in[2];
  const float* W_c      = (const float*)d_in[3];
  const float* W_hc     = (const float*)d_in[4];
  const float* W_ihat   = (const float*)d_in[5];
  const float* b_c      = (const float*)d_in[6];
  const float* b_ihat   = (const float*)d_in[7];
  const float* W_s      = (const float*)d_in[8];
  const float* W_hs     = (const float*)d_in[9];
  const float* W_i      = (const float*)d_in[10];
  const float* b_s      = (const float*)d_in[11];
  const float* b_i      = (const float*)d_in[12];
  const float* emb      = (const float*)d_in[13];
  const float* W_ih     = (const float*)d_in[14];
  const float* W_hh     = (const float*)d_in[15];
  const float* b_ih     = (const float*)d_in[16];
  const float* b_hh     = (const float*)d_in[17];
  const float* W_init_h = (const float*)d_in[18];
  const float* b_init_h = (const float*)d_in[19];
  const float* W_init_c = (const float*)d_in[20];
  const float* b_init_c = (const float*)d_in[21];
  const float* W_fc     = (const float*)d_in[22];
  const float* b_fc     = (const float*)d_in[23];
  float* out = (float*)d_out;

  static bool attr_set = false;
  if(!attr_set){
    cudaFuncSetAttribute(k_gates, cudaFuncAttributeMaxDynamicSharedMemorySize, BB*3072*4);
    attr_set = true;
  }

  k_vmean<<<2048,256>>>(enc);
  k_init<<<2048,128>>>(W_init_h, b_init_h, W_init_c, b_init_c);
  k_tail<<<25,256>>>(out, (long long)out_size, caps, caplen);

  for(int t=0;t<TT;t++){
    int hb = t & 1, nb = (t+1) & 1;
    k_hW<<<128,256>>>(W_hc, W_hs, hb);
    k_betafused<<<256,256>>>(W_c, b_c, W_ihat, b_ihat);
    k_einsum<<<dim3(4,8,8),256>>>(enc, W_s);
    k_alphalogit<<<64,256>>>(b_s, W_i, b_i);
    k_awe<<<dim3(256,8),256>>>(enc);
    k_gates<<<64,256,BB*3072*4>>>(W_ih, W_hh, b_ih, b_hh, emb, caps, t, hb, nb);
    k_preds<<<625,256>>>(W_fc, b_fc, out, t, nb);
  }
}